// round 16
// baseline (speedup 1.0000x reference)
#include <cuda_runtime.h>
#include <cuda_fp16.h>
#include <math.h>
#include <stdint.h>

// ---------------------------------------------------------------------------
// Problem constants
// ---------------------------------------------------------------------------
#define B_  32
#define T_  1024
#define D_  1024
#define U_  1024
#define M_  (B_ * T_)     // 32768
#define N_  (4 * U_)      // 4096
#define K_  D_            // 1024

// g layout: [B][tb=128][stream=4][U][ti=8], t = tb*8 + ti
__device__ __align__(16) __half g_half[(size_t)M_ * N_];          // 256 MB
__device__ __align__(16) __half Wt_h_g[(size_t)N_ * K_];          // 8 MB

// ---------------------------------------------------------------------------
// PTX helpers (base-target instructions only, no sm_103a feature gating)
// ---------------------------------------------------------------------------
__device__ __forceinline__ uint32_t smem_u32(const void* p) {
    uint32_t a;
    asm("{ .reg .u64 t; cvta.to.shared.u64 t, %1; cvt.u32.u64 %0, t; }" : "=r"(a) : "l"(p));
    return a;
}
__device__ __forceinline__ void cp_async16(uint32_t dst, const void* src) {
    asm volatile("cp.async.cg.shared.global [%0], [%1], 16;" :: "r"(dst), "l"(src));
}
__device__ __forceinline__ void cp_commit() {
    asm volatile("cp.async.commit_group;");
}
template <int N>
__device__ __forceinline__ void cp_wait() {
    asm volatile("cp.async.wait_group %0;" :: "n"(N));
}
__device__ __forceinline__ void ldsm_x4(uint32_t* r, uint32_t addr) {
    asm volatile("ldmatrix.sync.aligned.m8n8.x4.shared.b16 {%0,%1,%2,%3}, [%4];"
                 : "=r"(r[0]), "=r"(r[1]), "=r"(r[2]), "=r"(r[3]) : "r"(addr));
}
__device__ __forceinline__ void mma_16816_f16(float* d, const uint32_t* a,
                                              uint32_t b0, uint32_t b1) {
    asm volatile("mma.sync.aligned.m16n8k16.row.col.f32.f16.f16.f32 "
                 "{%0,%1,%2,%3}, {%4,%5,%6,%7}, {%8,%9}, {%0,%1,%2,%3};"
                 : "+f"(d[0]), "+f"(d[1]), "+f"(d[2]), "+f"(d[3])
                 : "r"(a[0]), "r"(a[1]), "r"(a[2]), "r"(a[3]), "r"(b0), "r"(b1));
}
__device__ __forceinline__ float2 h2f2(uint32_t u) {
    __half2 h = *reinterpret_cast<__half2*>(&u);
    return __half22float2(h);
}

// ---------------------------------------------------------------------------
// Prep: transpose W [K,N] -> Wt [N,K] fp16
// ---------------------------------------------------------------------------
__global__ __launch_bounds__(1024)
void transpose_w_kernel(const float* __restrict__ W) {
    __shared__ float tile[32][33];
    const int n0 = blockIdx.x * 32;
    const int k0 = blockIdx.y * 32;
    const int tx = threadIdx.x, ty = threadIdx.y;
    tile[ty][tx] = W[(size_t)(k0 + ty) * N_ + (n0 + tx)];
    __syncthreads();
    Wt_h_g[(size_t)(n0 + ty) * K_ + (k0 + tx)] = __float2half_rn(tile[tx][ty]);
}

// ---------------------------------------------------------------------------
// HMMA GEMM with fused x->fp16 conversion (uniform-lead pipeline):
//   g = half(half(x) @ Wt^T + bias), scan-layout store.
// Group G_k = {x_k fp32 (3-slot ring), B_k fp16 (4-slot ring)}, committed at
// iter k-3. Top of iter: wait_group<1> + barrier. MMA over A16[it%2]/B[it%4];
// then each thread converts ITS OWN 16 floats of x_{it+1} -> A16[(it+1)%2]
// (no extra barrier; published by next iteration's barrier). 2 CTAs/SM.
// ---------------------------------------------------------------------------
#define BM 128
#define BN 128
#define BKQ 32
#define KPAD 40                    // padded fp16 row (elems) -> 80B rows
#define NITER (K_ / BKQ)           // 32

#define X_SLOT_B 16384             // 128 rows x 32 fp32
#define B_SLOT_B (BN * KPAD * 2)   // 10240
#define A_SLOT_B (BM * KPAD * 2)   // 10240
#define SX    0
#define SB    (3 * X_SLOT_B)                     // 49152
#define SA16  (SB + 4 * B_SLOT_B)                // 90112
#define GEMM_SMEM (SA16 + 2 * A_SLOT_B)          // 110592 (x2 = 221184/SM)

__global__ __launch_bounds__(256, 2)
void sru_gemm_mma_kernel(const float* __restrict__ X,
                         const __half* __restrict__ Bh,
                         const float* __restrict__ bias) {
    extern __shared__ char smem[];
    const uint32_t sb = smem_u32(smem);
    const int tid = threadIdx.x;
    const int lane = tid & 31;
    const int wid = tid >> 5;
    const int wm = wid & 1;        // 0..1  (M warps, 64 rows each)
    const int wn = wid >> 1;       // 0..3  (N warps, 32 cols each)
    const int m_blk = blockIdx.y * BM;
    const int n_blk = blockIdx.x * BN;

    float acc[4][4][4];            // [m16 tile][n8 tile][frag]
    #pragma unroll
    for (int i = 0; i < 4; i++)
        #pragma unroll
        for (int j = 0; j < 4; j++)
            #pragma unroll
            for (int r = 0; r < 4; r++)
                acc[i][j][r] = 0.0f;

    // this thread's own x rows: xrow = tid>>1 (0..127), 16 floats at xcol
    const int xrow = tid >> 1;
    const int xcol = (tid & 1) * 16;
    const float* xg = X + (size_t)(m_blk + xrow) * K_ + xcol;

    // ---- group loader: x_k (fp32, slot k%3) + B_k (fp16, slot k%4) ----
    auto load_group = [&](int k) {
        const int k0 = k * BKQ;
        const uint32_t xs = sb + SX + (k % 3) * X_SLOT_B + (uint32_t)tid * 64;
        #pragma unroll
        for (int i = 0; i < 4; i++)
            cp_async16(xs + i * 16, xg + k0 + i * 4);
        const uint32_t bs = sb + SB + (k % 4) * B_SLOT_B;
        #pragma unroll
        for (int i = 0; i < 2; i++) {
            const int ch = tid + 256 * i;
            const int r = ch >> 2, c = ch & 3;
            cp_async16(bs + (uint32_t)(r * KPAD * 2 + c * 16),
                       Bh + (size_t)(n_blk + r) * K_ + k0 + c * 8);
        }
        cp_commit();
    };

    // convert own 16 fp32 of x_k (staging slot k%3) -> A16 slot a
    auto convert = [&](int a, int k) {
        const float4* src = reinterpret_cast<const float4*>(
            smem + SX + (k % 3) * X_SLOT_B + tid * 64);
        float4 v0 = src[0], v1 = src[1], v2 = src[2], v3 = src[3];
        __half2 h0 = __floats2half2_rn(v0.x, v0.y);
        __half2 h1 = __floats2half2_rn(v0.z, v0.w);
        __half2 h2 = __floats2half2_rn(v1.x, v1.y);
        __half2 h3 = __floats2half2_rn(v1.z, v1.w);
        __half2 h4 = __floats2half2_rn(v2.x, v2.y);
        __half2 h5 = __floats2half2_rn(v2.z, v2.w);
        __half2 h6 = __floats2half2_rn(v3.x, v3.y);
        __half2 h7 = __floats2half2_rn(v3.z, v3.w);
        uint4 d0, d1;
        d0.x = *reinterpret_cast<uint32_t*>(&h0);
        d0.y = *reinterpret_cast<uint32_t*>(&h1);
        d0.z = *reinterpret_cast<uint32_t*>(&h2);
        d0.w = *reinterpret_cast<uint32_t*>(&h3);
        d1.x = *reinterpret_cast<uint32_t*>(&h4);
        d1.y = *reinterpret_cast<uint32_t*>(&h5);
        d1.z = *reinterpret_cast<uint32_t*>(&h6);
        d1.w = *reinterpret_cast<uint32_t*>(&h7);
        uint4* dst = reinterpret_cast<uint4*>(
            smem + SA16 + a * A_SLOT_B + xrow * (KPAD * 2) + (tid & 1) * 32);
        dst[0] = d0;
        dst[1] = d1;
    };

    // ---- prologue: G0..G2 in flight; convert A16[0] from x_0 ----
    load_group(0);
    load_group(1);
    load_group(2);
    cp_wait<2>();        // G0 complete
    convert(0, 0);       // published by iter-0 barrier

    for (int it = 0; it < NITER; it++) {
        cp_wait<1>();    // G_it, G_{it+1} complete; G_{it+2} may be in flight
        __syncthreads(); // publish A16[it%2] conversion + B[it%4] arrival;
                         // also orders last iter's reads before slot reuse

        const uint32_t stA = sb + SA16 + (it % 2) * A_SLOT_B;
        const uint32_t stB = sb + SB + (it % 4) * B_SLOT_B;
        #pragma unroll
        for (int ks = 0; ks < 2; ks++) {
            uint32_t aH[4][4];
            const int arow = wm * 64 + (lane & 15);
            const int acol = ks * 16 + (lane >> 4) * 8;
            #pragma unroll
            for (int mt = 0; mt < 4; mt++)
                ldsm_x4(aH[mt], stA + (uint32_t)(((arow + mt * 16) * KPAD + acol) * 2));

            const int brow = wn * 32 + (lane & 15);
            #pragma unroll
            for (int nt2 = 0; nt2 < 2; nt2++) {
                uint32_t bh[4];
                ldsm_x4(bh, stB + (uint32_t)(((brow + nt2 * 16) * KPAD + acol) * 2));
                #pragma unroll
                for (int mt = 0; mt < 4; mt++) {
                    mma_16816_f16(acc[mt][2 * nt2],     aH[mt], bh[0], bh[2]);
                    mma_16816_f16(acc[mt][2 * nt2 + 1], aH[mt], bh[1], bh[3]);
                }
            }
        }
        // convert x_{it+1} (complete per wait<1>) into the other A16 slot;
        // consumed next iteration after its barrier.
        if (it + 1 < NITER) convert((it + 1) % 2, it + 1);
        // prefetch group it+3 (x slot (it+3)%3 last converted at iter it-1 <
        // now; B slot (it+3)%4 last read at iter it-1, ordered by barrier)
        if (it + 3 < NITER) load_group(it + 3);
    }

    // ---- epilogue: bias + fp16 store into scan layout ----
    const int bI = m_blk >> 10;
    const int sI = n_blk >> 10;
    const int ti = lane >> 2;
    const int tBase = (m_blk & 1023) + wm * 64;
    const int uBase = (n_blk & 1023) + wn * 32;
    #pragma unroll
    for (int nt = 0; nt < 4; nt++) {
        const int col = n_blk + wn * 32 + nt * 8 + (lane & 3) * 2;
        const float bx = __ldg(&bias[col]);
        const float by = __ldg(&bias[col + 1]);
        const int u0 = uBase + nt * 8 + (lane & 3) * 2;
        #pragma unroll
        for (int mt = 0; mt < 4; mt++) {
            const int tl = tBase + mt * 16 + ti;
            const size_t base = (((size_t)bI * 128 + (tl >> 3)) * 4 + sI) * 1024;
            g_half[(base + u0)     * 8 + ti] = __float2half_rn(acc[mt][nt][0] + bx);
            g_half[(base + u0 + 1) * 8 + ti] = __float2half_rn(acc[mt][nt][1] + by);
            g_half[(base + 4096 + u0)     * 8 + ti] = __float2half_rn(acc[mt][nt][2] + bx);
            g_half[(base + 4096 + u0 + 1) * 8 + ti] = __float2half_rn(acc[mt][nt][3] + by);
        }
    }
}

// ---------------------------------------------------------------------------
// SRU scan over the [B][tb][s][U][8] layout (proven R7/R12 config):
// 8 LDG.128 per 16 timesteps, register double buffer, no barriers.
// ---------------------------------------------------------------------------
struct ScanBuf { uint4 q[2][4]; };   // [tb][stream], 8 halves (ti) each

__device__ __forceinline__ void scan_load(ScanBuf& bf, const uint4* __restrict__ gq,
                                          int tb0) {
    #pragma unroll
    for (int i = 0; i < 2; i++)
        #pragma unroll
        for (int s = 0; s < 4; s++)
            bf.q[i][s] = __ldcs(gq + ((size_t)(tb0 + i) * 4 + s) * 1024);
}

__device__ __forceinline__ void unpack8(float* a, uint4 q) {
    float2 t;
    t = h2f2(q.x); a[0] = t.x; a[1] = t.y;
    t = h2f2(q.y); a[2] = t.x; a[3] = t.y;
    t = h2f2(q.z); a[4] = t.x; a[5] = t.y;
    t = h2f2(q.w); a[6] = t.x; a[7] = t.y;
}

__device__ __forceinline__ void scan_compute(const ScanBuf& bf, float& c,
                                             float vr, float vf,
                                             float* __restrict__ orow, int t0) {
    #pragma unroll
    for (int i = 0; i < 2; i++) {
        float a1[8], a2[8], a3[8], a4[8];
        unpack8(a1, bf.q[i][0]);
        unpack8(a2, bf.q[i][1]);
        unpack8(a3, bf.q[i][2]);
        unpack8(a4, bf.q[i][3]);
        #pragma unroll
        for (int ti = 0; ti < 8; ti++) {
            const float fg = __fdividef(1.0f, 1.0f + __expf(-(a1[ti] + vf * c)));
            const float r  = __fdividef(1.0f, 1.0f + __expf(-(a3[ti] + vr * c)));
            const float cn = fg * c + (1.0f - fg) * a2[ti];
            const float h  = r * cn + (1.0f - r) * a4[ti];
            c = cn;
            __stcs(orow + (size_t)(t0 + i * 8 + ti) * U_, h);
        }
    }
}

__global__ __launch_bounds__(256)
void sru_scan_kernel(const float* __restrict__ c0,
                     const float* __restrict__ Vr,
                     const float* __restrict__ Vf,
                     float* __restrict__ out) {
    const int idx = blockIdx.x * blockDim.x + threadIdx.x;  // 0 .. B*U-1
    const int b = idx >> 10;
    const int u = idx & (U_ - 1);

    float c = c0[idx];
    const float vr = Vr[u];
    const float vf = Vf[u];

    const uint4* gq = reinterpret_cast<const uint4*>(g_half)
                      + (size_t)b * 128 * 4 * 1024 + u;
    float* orow = out + (size_t)b * T_ * U_ + u;

    ScanBuf bufA, bufB;
    scan_load(bufA, gq, 0);

    #pragma unroll 1
    for (int t0 = 0; t0 < T_; t0 += 32) {
        scan_load(bufB, gq, (t0 >> 3) + 2);
        scan_compute(bufA, c, vr, vf, orow, t0);
        if (t0 + 32 < T_) scan_load(bufA, gq, (t0 >> 3) + 4);
        scan_compute(bufB, c, vr, vf, orow, t0 + 16);
    }
}

// ---------------------------------------------------------------------------
// Host launch.  Inputs: x, h0, c0, W, b, Vr, Vf  — strictly serial, one stream
// ---------------------------------------------------------------------------
extern "C" void kernel_launch(void* const* d_in, const int* in_sizes, int n_in,
                              void* d_out, int out_size) {
    const float* x  = (const float*)d_in[0];
    // d_in[1] = h0 (unused by reference)
    const float* c0 = (const float*)d_in[2];
    const float* W  = (const float*)d_in[3];
    const float* b  = (const float*)d_in[4];
    const float* Vr = (const float*)d_in[5];
    const float* Vf = (const float*)d_in[6];
    float* out = (float*)d_out;

    static bool attr_set = false;
    if (!attr_set) {
        cudaFuncSetAttribute(sru_gemm_mma_kernel,
                             cudaFuncAttributeMaxDynamicSharedMemorySize, GEMM_SMEM);
        attr_set = true;
    }

    void* pBh;
    cudaGetSymbolAddress(&pBh, Wt_h_g);

    // Prep: transpose+round W (x conversion fused into GEMM)
    transpose_w_kernel<<<dim3(N_ / 32, K_ / 32), dim3(32, 32)>>>(W);

    // Fused-convert fp16 HMMA GEMM (fp32 accum, 2 CTAs/SM)
    dim3 gg(N_ / BN, M_ / BM);  // (32, 256)
    sru_gemm_mma_kernel<<<gg, 256, GEMM_SMEM>>>(x, (const __half*)pBh, b);

    // Scan (proven R12 config)
    sru_scan_kernel<<<(B_ * U_) / 256, 256>>>(c0, Vr, Vf, out);
}

// round 17
// speedup vs baseline: 1.4309x; 1.4309x over previous
#include <cuda_runtime.h>
#include <cuda_fp16.h>
#include <math.h>
#include <stdint.h>

// ---------------------------------------------------------------------------
// Problem constants
// ---------------------------------------------------------------------------
#define B_  32
#define T_  1024
#define D_  1024
#define U_  1024
#define M_  (B_ * T_)     // 32768
#define N_  (4 * U_)      // 4096
#define K_  D_            // 1024

// g layout: [B][tb=128][stream=4][U][ti=8], t = tb*8 + ti
// stream 2 (r-gate arg) is pre-scaled by 0.5 for the tanh sigmoid identity.
__device__ __align__(16) __half g_half[(size_t)M_ * N_];          // 256 MB
__device__ __align__(16) __half A_h_g[(size_t)M_ * K_];           // 64 MB
__device__ __align__(16) __half Wt_h_g[(size_t)N_ * K_];          // 8 MB

// ---------------------------------------------------------------------------
// PTX helpers (base-target instructions only, no sm_103a feature gating)
// ---------------------------------------------------------------------------
__device__ __forceinline__ uint32_t smem_u32(const void* p) {
    uint32_t a;
    asm("{ .reg .u64 t; cvta.to.shared.u64 t, %1; cvt.u32.u64 %0, t; }" : "=r"(a) : "l"(p));
    return a;
}
__device__ __forceinline__ void cp_async16(uint32_t dst, const void* src) {
    asm volatile("cp.async.cg.shared.global [%0], [%1], 16;" :: "r"(dst), "l"(src));
}
__device__ __forceinline__ void cp_commit() {
    asm volatile("cp.async.commit_group;");
}
template <int N>
__device__ __forceinline__ void cp_wait() {
    asm volatile("cp.async.wait_group %0;" :: "n"(N));
}
__device__ __forceinline__ void ldsm_x4(uint32_t* r, uint32_t addr) {
    asm volatile("ldmatrix.sync.aligned.m8n8.x4.shared.b16 {%0,%1,%2,%3}, [%4];"
                 : "=r"(r[0]), "=r"(r[1]), "=r"(r[2]), "=r"(r[3]) : "r"(addr));
}
__device__ __forceinline__ void mma_16816_f16(float* d, const uint32_t* a,
                                              uint32_t b0, uint32_t b1) {
    asm volatile("mma.sync.aligned.m16n8k16.row.col.f32.f16.f16.f32 "
                 "{%0,%1,%2,%3}, {%4,%5,%6,%7}, {%8,%9}, {%0,%1,%2,%3};"
                 : "+f"(d[0]), "+f"(d[1]), "+f"(d[2]), "+f"(d[3])
                 : "r"(a[0]), "r"(a[1]), "r"(a[2]), "r"(a[3]), "r"(b0), "r"(b1));
}
__device__ __forceinline__ float2 h2f2(uint32_t u) {
    __half2 h = *reinterpret_cast<__half2*>(&u);
    return __half22float2(h);
}
__device__ __forceinline__ float tanh_approx(float x) {
    float y;
    asm("tanh.approx.f32 %0, %1;" : "=f"(y) : "f"(x));
    return y;
}

// ---------------------------------------------------------------------------
// Prep 1: round x (fp32 [M,K]) to fp16
// ---------------------------------------------------------------------------
__global__ __launch_bounds__(256)
void split_x_kernel(const float* __restrict__ x) {
    size_t i = ((size_t)blockIdx.x * blockDim.x + threadIdx.x) * 4;
    float4 v = *reinterpret_cast<const float4*>(x + i);
    __half2* p = reinterpret_cast<__half2*>(A_h_g + i);
    p[0] = __halves2half2(__float2half_rn(v.x), __float2half_rn(v.y));
    p[1] = __halves2half2(__float2half_rn(v.z), __float2half_rn(v.w));
}

// ---------------------------------------------------------------------------
// Prep 2: transpose W [K,N] -> Wt [N,K] fp16
// ---------------------------------------------------------------------------
__global__ __launch_bounds__(1024)
void transpose_w_kernel(const float* __restrict__ W) {
    __shared__ float tile[32][33];
    const int n0 = blockIdx.x * 32;
    const int k0 = blockIdx.y * 32;
    const int tx = threadIdx.x, ty = threadIdx.y;
    tile[ty][tx] = W[(size_t)(k0 + ty) * N_ + (n0 + tx)];
    __syncthreads();
    Wt_h_g[(size_t)(n0 + ty) * K_ + (k0 + tx)] = __float2half_rn(tile[tx][ty]);
}

// ---------------------------------------------------------------------------
// HMMA GEMM (single-pass fp16, fp32 accum): g = half((Ah @ Bh^T + bias)*sc),
// sc = 0.5 for the r-gate stream (2), else 1. Scan-layout store.
// BM=128, BN=128, 256 threads, 5-stage cp.async pipeline, 2 CTAs/SM.
// (R12/R15-proven mainloop: ~929us)
// ---------------------------------------------------------------------------
#define BM 128
#define BN 128
#define BKQ 32
#define KPAD 40                    // padded smem row (elems) -> 80B rows
#define NSTAGE 5
#define NITER (K_ / BKQ)           // 32

#define SA    0
#define SBH   (BM * KPAD * 2)                    // 10240
#define STAGE_BYTES (SBH + BN * KPAD * 2)        // 20480
#define GEMM_SMEM (NSTAGE * STAGE_BYTES)         // 102400 (x2 CTAs = 204800/SM)

__global__ __launch_bounds__(256, 2)
void sru_gemm_mma_kernel(const __half* __restrict__ Ah,
                         const __half* __restrict__ Bh,
                         const float* __restrict__ bias) {
    extern __shared__ char smem[];
    const uint32_t sb = smem_u32(smem);
    const int tid = threadIdx.x;
    const int lane = tid & 31;
    const int wid = tid >> 5;
    const int wm = wid & 1;        // 0..1  (M warps, 64 rows each)
    const int wn = wid >> 1;       // 0..3  (N warps, 32 cols each)
    const int m_blk = blockIdx.y * BM;
    const int n_blk = blockIdx.x * BN;

    float acc[4][4][4];            // [m16 tile][n8 tile][frag]
    #pragma unroll
    for (int i = 0; i < 4; i++)
        #pragma unroll
        for (int j = 0; j < 4; j++)
            #pragma unroll
            for (int r = 0; r < 4; r++)
                acc[i][j][r] = 0.0f;

    // ---- stage loader (4 cp.async of 16B per thread) ----
    auto load_stage = [&](int s, int k0) {
        const uint32_t st = sb + s * STAGE_BYTES;
        #pragma unroll
        for (int i = 0; i < 2; i++) {              // A: 512 chunks
            const int ch = tid + 256 * i;
            const int r = ch >> 2, c = ch & 3;
            cp_async16(st + SA + (uint32_t)(r * KPAD * 2 + c * 16),
                       Ah + (size_t)(m_blk + r) * K_ + k0 + c * 8);
        }
        #pragma unroll
        for (int i = 0; i < 2; i++) {              // B: 512 chunks
            const int ch = tid + 256 * i;
            const int r = ch >> 2, c = ch & 3;
            cp_async16(st + SBH + (uint32_t)(r * KPAD * 2 + c * 16),
                       Bh + (size_t)(n_blk + r) * K_ + k0 + c * 8);
        }
    };

    // prologue: stages 0..3
    load_stage(0, 0);          cp_commit();
    load_stage(1, BKQ);        cp_commit();
    load_stage(2, 2 * BKQ);    cp_commit();
    load_stage(3, 3 * BKQ);    cp_commit();

    for (int it = 0; it < NITER; it++) {
        cp_wait<3>();
        __syncthreads();   // readers of stage (it-1)%5 done + stage (it)%5 visible

        const uint32_t st = sb + (it % NSTAGE) * STAGE_BYTES;
        #pragma unroll
        for (int ks = 0; ks < 2; ks++) {
            uint32_t aH[4][4];
            const int arow = wm * 64 + (lane & 15);
            const int acol = ks * 16 + (lane >> 4) * 8;
            #pragma unroll
            for (int mt = 0; mt < 4; mt++)
                ldsm_x4(aH[mt], st + SA + (uint32_t)(((arow + mt * 16) * KPAD + acol) * 2));

            const int brow = wn * 32 + (lane & 15);
            #pragma unroll
            for (int nt2 = 0; nt2 < 2; nt2++) {
                uint32_t bh[4];
                ldsm_x4(bh, st + SBH + (uint32_t)(((brow + nt2 * 16) * KPAD + acol) * 2));
                #pragma unroll
                for (int mt = 0; mt < 4; mt++) {
                    mma_16816_f16(acc[mt][2 * nt2],     aH[mt], bh[0], bh[2]);
                    mma_16816_f16(acc[mt][2 * nt2 + 1], aH[mt], bh[1], bh[3]);
                }
            }
        }
        // next iteration's top barrier orders these reads before the overwrite
        if (it + 4 < NITER) load_stage((it + 4) % NSTAGE, (it + 4) * BKQ);
        cp_commit();
    }

    // ---- epilogue: bias, r-stream 0.5 scale, fp16 store into scan layout ----
    const int bI = m_blk >> 10;
    const int sI = n_blk >> 10;
    const float sc = (sI == 2) ? 0.5f : 1.0f;   // r-gate: sigmoid via tanh(x/2)
    const int ti = lane >> 2;
    const int tBase = (m_blk & 1023) + wm * 64;
    const int uBase = (n_blk & 1023) + wn * 32;
    #pragma unroll
    for (int nt = 0; nt < 4; nt++) {
        const int col = n_blk + wn * 32 + nt * 8 + (lane & 3) * 2;
        const float bx = __ldg(&bias[col]);
        const float by = __ldg(&bias[col + 1]);
        const int u0 = uBase + nt * 8 + (lane & 3) * 2;
        #pragma unroll
        for (int mt = 0; mt < 4; mt++) {
            const int tl = tBase + mt * 16 + ti;
            const size_t base = (((size_t)bI * 128 + (tl >> 3)) * 4 + sI) * 1024;
            g_half[(base + u0)     * 8 + ti] = __float2half_rn((acc[mt][nt][0] + bx) * sc);
            g_half[(base + u0 + 1) * 8 + ti] = __float2half_rn((acc[mt][nt][1] + by) * sc);
            g_half[(base + 4096 + u0)     * 8 + ti] = __float2half_rn((acc[mt][nt][2] + bx) * sc);
            g_half[(base + 4096 + u0 + 1) * 8 + ti] = __float2half_rn((acc[mt][nt][3] + by) * sc);
        }
    }
}

// ---------------------------------------------------------------------------
// SRU scan over the [B][tb][s][U][8] layout (R12-proven structure):
// 8 LDG.128 per 16 timesteps, register double buffer, no barriers.
// f-gate: exact path (expf + fdividef) -> c-chain bit-identical to R15.
// r-gate: sigmoid(x) = 0.5 + 0.5*tanh(x/2), ONE MUFU (a3 pre-scaled by 0.5).
// ---------------------------------------------------------------------------
struct ScanBuf { uint4 q[2][4]; };   // [tb][stream], 8 halves (ti) each

__device__ __forceinline__ void scan_load(ScanBuf& bf, const uint4* __restrict__ gq,
                                          int tb0) {
    #pragma unroll
    for (int i = 0; i < 2; i++)
        #pragma unroll
        for (int s = 0; s < 4; s++)
            bf.q[i][s] = __ldcs(gq + ((size_t)(tb0 + i) * 4 + s) * 1024);
}

__device__ __forceinline__ void unpack8(float* a, uint4 q) {
    float2 t;
    t = h2f2(q.x); a[0] = t.x; a[1] = t.y;
    t = h2f2(q.y); a[2] = t.x; a[3] = t.y;
    t = h2f2(q.z); a[4] = t.x; a[5] = t.y;
    t = h2f2(q.w); a[6] = t.x; a[7] = t.y;
}

__device__ __forceinline__ void scan_compute(const ScanBuf& bf, float& c,
                                             float vr2, float vf,
                                             float* __restrict__ orow, int t0) {
    #pragma unroll
    for (int i = 0; i < 2; i++) {
        float a1[8], a2[8], a3[8], a4[8];
        unpack8(a1, bf.q[i][0]);
        unpack8(a2, bf.q[i][1]);
        unpack8(a3, bf.q[i][2]);   // pre-scaled by 0.5 in the GEMM epilogue
        unpack8(a4, bf.q[i][3]);
        #pragma unroll
        for (int ti = 0; ti < 8; ti++) {
            const float fg = __fdividef(1.0f, 1.0f + __expf(-(a1[ti] + vf * c)));
            const float r  = fmaf(0.5f, tanh_approx(a3[ti] + vr2 * c), 0.5f);
            const float cn = fg * c + (1.0f - fg) * a2[ti];
            const float h  = fmaf(r, cn - a4[ti], a4[ti]);
            c = cn;
            __stcs(orow + (size_t)(t0 + i * 8 + ti) * U_, h);
        }
    }
}

__global__ __launch_bounds__(256)
void sru_scan_kernel(const float* __restrict__ c0,
                     const float* __restrict__ Vr,
                     const float* __restrict__ Vf,
                     float* __restrict__ out) {
    const int idx = blockIdx.x * blockDim.x + threadIdx.x;  // 0 .. B*U-1
    const int b = idx >> 10;
    const int u = idx & (U_ - 1);

    float c = c0[idx];
    const float vr2 = Vr[u] * 0.5f;   // matches the 0.5-scaled a3 stream
    const float vf = Vf[u];

    const uint4* gq = reinterpret_cast<const uint4*>(g_half)
                      + (size_t)b * 128 * 4 * 1024 + u;
    float* orow = out + (size_t)b * T_ * U_ + u;

    ScanBuf bufA, bufB;
    scan_load(bufA, gq, 0);

    #pragma unroll 1
    for (int t0 = 0; t0 < T_; t0 += 32) {
        scan_load(bufB, gq, (t0 >> 3) + 2);
        scan_compute(bufA, c, vr2, vf, orow, t0);
        if (t0 + 32 < T_) scan_load(bufA, gq, (t0 >> 3) + 4);
        scan_compute(bufB, c, vr2, vf, orow, t0 + 16);
    }
}

// ---------------------------------------------------------------------------
// Host launch.  Inputs: x, h0, c0, W, b, Vr, Vf
// Prep kernels overlapped via R15-proven event-forked side stream.
// ---------------------------------------------------------------------------
extern "C" void kernel_launch(void* const* d_in, const int* in_sizes, int n_in,
                              void* d_out, int out_size) {
    const float* x  = (const float*)d_in[0];
    // d_in[1] = h0 (unused by reference)
    const float* c0 = (const float*)d_in[2];
    const float* W  = (const float*)d_in[3];
    const float* b  = (const float*)d_in[4];
    const float* Vr = (const float*)d_in[5];
    const float* Vf = (const float*)d_in[6];
    float* out = (float*)d_out;

    static cudaStream_t s1 = nullptr;
    static cudaEvent_t evFork, evJoin;
    if (s1 == nullptr) {
        cudaStreamCreateWithFlags(&s1, cudaStreamNonBlocking);
        cudaEventCreateWithFlags(&evFork, cudaEventDisableTiming);
        cudaEventCreateWithFlags(&evJoin, cudaEventDisableTiming);
        cudaFuncSetAttribute(sru_gemm_mma_kernel,
                             cudaFuncAttributeMaxDynamicSharedMemorySize, GEMM_SMEM);
    }

    void *pAh, *pBh;
    cudaGetSymbolAddress(&pAh, A_h_g);
    cudaGetSymbolAddress(&pBh, Wt_h_g);

    // Fork: transpose_w on side stream, split_x on capture stream, join.
    cudaEventRecord(evFork, 0);
    cudaStreamWaitEvent(s1, evFork, 0);
    transpose_w_kernel<<<dim3(N_ / 32, K_ / 32), dim3(32, 32), 0, s1>>>(W);
    cudaEventRecord(evJoin, s1);
    split_x_kernel<<<(int)((size_t)M_ * K_ / 4 / 256), 256>>>(x);
    cudaStreamWaitEvent(0, evJoin, 0);

    // Single-pass fp16 HMMA GEMM (fp32 accum, 2 CTAs/SM)
    dim3 gg(N_ / BN, M_ / BM);  // (32, 256)
    sru_gemm_mma_kernel<<<gg, 256, GEMM_SMEM>>>(
        (const __half*)pAh, (const __half*)pBh, b);

    // Scan (R12 structure, r-gate via tanh.approx)
    sru_scan_kernel<<<(B_ * U_) / 256, 256>>>(c0, Vr, Vf, out);
}